// round 2
// baseline (speedup 1.0000x reference)
#include <cuda_runtime.h>
#include <math.h>

// Problem constants
#define B_  32
#define S_  2048
#define H_  1024
#define M_  (S_ * B_)      // 65536 rows of flattened key (s-major, b inner)
#define NB_ (H_ / 128)     // 8 n-tiles
#define SC_ 16             // s-chunks for the context split-K

// Device scratch (no allocations allowed)
__device__ float g_qw[B_ * H_];            // q@Wa + Wa_b + Ua_b          (128 KB)
__device__ float g_part[NB_ * M_];         // per-n-tile score partials   (2 MB)
__device__ float g_ctxp[SC_ * B_ * H_];    // context split-K partials    (2 MB)
__device__ float g_wfallback[B_ * S_];     // weights scratch if out_size only holds context

// ---------------------------------------------------------------------------
// Kernel 1: qw[b][n] = Wa_b[n] + Ua_b[n] + sum_k q[b][k] * Wa[k][n]
// grid (H/256, B), 256 threads
// ---------------------------------------------------------------------------
__global__ void qw_kernel(const float* __restrict__ q,
                          const float* __restrict__ Wa,
                          const float* __restrict__ Wab,
                          const float* __restrict__ Uab) {
    int b = blockIdx.y;
    int n = blockIdx.x * 256 + threadIdx.x;
    const float* qb = q + b * H_;
    float acc = Wab[n] + Uab[n];
#pragma unroll 4
    for (int k = 0; k < H_; k++)
        acc += qb[k] * Wa[k * H_ + n];
    g_qw[b * H_ + n] = acc;
}

// ---------------------------------------------------------------------------
// Kernel 2: fused energy GEMM.
// C[m][n] = key_flat[m][:] dot Ua[:][n]  (m = s*B + b)
// part[nb][m] = sum_{n in tile nb} va[n] * tanh(C[m][n] + qw[m%B][n])
// 128x128x16 tile, 256 threads, 8x8 per thread.
// grid (8 n-tiles, 512 m-tiles)  -> adjacent CTAs share the key tile via L2.
// ---------------------------------------------------------------------------
__global__ __launch_bounds__(256, 2)
void energy_kernel(const float* __restrict__ key,
                   const float* __restrict__ Ua,
                   const float* __restrict__ va) {
    __shared__ float As[16][132];   // transposed A tile, padded
    __shared__ float Bs[16][128];
    __shared__ float Qs[32][128];   // qw slice for this n-tile

    const int tid = threadIdx.x;
    const int tx  = tid & 15;       // n dim
    const int ty  = tid >> 4;       // m dim
    const int nb  = blockIdx.x;     // 0..7
    const int n0  = nb * 128;
    const int m0  = blockIdx.y * 128;

    // stage qw[0..31][n0..n0+127] into smem (4096 floats)
#pragma unroll
    for (int u = 0; u < 4; u++) {
        int lv  = tid + u * 256;          // float4 unit index, 0..1023
        int bb  = lv >> 5;                // 0..31
        int nn4 = (lv & 31) << 2;         // 0..124
        *(float4*)&Qs[bb][nn4] = *(const float4*)&g_qw[bb * H_ + n0 + nn4];
    }

    float va_f[8];
    *(float4*)&va_f[0] = *(const float4*)&va[n0 + tx * 8];
    *(float4*)&va_f[4] = *(const float4*)&va[n0 + tx * 8 + 4];

    float acc[8][8];
#pragma unroll
    for (int i = 0; i < 8; i++)
#pragma unroll
        for (int j = 0; j < 8; j++) acc[i][j] = 0.f;

    for (int kt = 0; kt < H_; kt += 16) {
        // A tile: 128 rows x 16 k, stored transposed As[k][m]
#pragma unroll
        for (int u = 0; u < 2; u++) {
            int t   = tid + u * 256;
            int row = t >> 2;             // 0..127
            int kc  = (t & 3) << 2;       // 0,4,8,12
            float4 v = *(const float4*)&key[(m0 + row) * H_ + kt + kc];
            As[kc + 0][row] = v.x;
            As[kc + 1][row] = v.y;
            As[kc + 2][row] = v.z;
            As[kc + 3][row] = v.w;
        }
        // B tile: 16 rows x 128 n
#pragma unroll
        for (int u = 0; u < 2; u++) {
            int t   = tid + u * 256;
            int row = t >> 5;             // 0..15
            int c4  = (t & 31) << 2;      // 0..124
            *(float4*)&Bs[row][c4] = *(const float4*)&Ua[(kt + row) * H_ + n0 + c4];
        }
        __syncthreads();

#pragma unroll
        for (int k = 0; k < 16; k++) {
            float a[8], bf[8];
            *(float4*)&a[0]  = *(float4*)&As[k][ty * 8];
            *(float4*)&a[4]  = *(float4*)&As[k][ty * 8 + 4];
            *(float4*)&bf[0] = *(float4*)&Bs[k][tx * 8];
            *(float4*)&bf[4] = *(float4*)&Bs[k][tx * 8 + 4];
#pragma unroll
            for (int i = 0; i < 8; i++)
#pragma unroll
                for (int j = 0; j < 8; j++)
                    acc[i][j] = fmaf(a[i], bf[j], acc[i][j]);
        }
        __syncthreads();
    }

    // Epilogue: tanh, weight by va, reduce the 128-wide n-tile per row.
#pragma unroll
    for (int i = 0; i < 8; i++) {
        int bb = (ty * 8 + i) & 31;       // m0 is a multiple of 128 -> of 32
        float rs = 0.f;
#pragma unroll
        for (int j = 0; j < 8; j++)
            rs += va_f[j] * tanhf(acc[i][j] + Qs[bb][tx * 8 + j]);
        // reduce across the 16 tx lanes (stay within 16-lane half-warp groups)
#pragma unroll
        for (int o = 8; o; o >>= 1)
            rs += __shfl_xor_sync(0xffffffffu, rs, o);
        if (tx == 0)
            g_part[nb * M_ + m0 + ty * 8 + i] = rs;
    }
}

// ---------------------------------------------------------------------------
// Kernel 3: softmax over S per batch. 32 blocks, 256 threads, 8 s per thread.
// Writes weights[b][s].  (va_b dropped: softmax is shift-invariant.)
// ---------------------------------------------------------------------------
__global__ void softmax_kernel(float* __restrict__ wout) {
    int b   = blockIdx.x;
    int tid = threadIdx.x;
    __shared__ float red[256];

    float sc[8];
#pragma unroll
    for (int u = 0; u < 8; u++) {
        int s = tid + u * 256;
        float v = 0.f;
#pragma unroll
        for (int nb = 0; nb < NB_; nb++)
            v += g_part[nb * M_ + s * B_ + b];
        sc[u] = v;
    }

    float mx = sc[0];
#pragma unroll
    for (int u = 1; u < 8; u++) mx = fmaxf(mx, sc[u]);
    red[tid] = mx;
    __syncthreads();
    for (int o = 128; o; o >>= 1) {
        if (tid < o) red[tid] = fmaxf(red[tid], red[tid + o]);
        __syncthreads();
    }
    mx = red[0];
    __syncthreads();

    float e[8];
    float sum = 0.f;
#pragma unroll
    for (int u = 0; u < 8; u++) {
        e[u] = expf(sc[u] - mx);
        sum += e[u];
    }
    red[tid] = sum;
    __syncthreads();
    for (int o = 128; o; o >>= 1) {
        if (tid < o) red[tid] += red[tid + o];
        __syncthreads();
    }
    float inv = 1.f / red[0];
#pragma unroll
    for (int u = 0; u < 8; u++)
        wout[b * S_ + tid + u * 256] = e[u] * inv;
}

// ---------------------------------------------------------------------------
// Kernel 4: context split-K.  grid (16 s-chunks, 32 b), 256 threads (4 h each).
// g_ctxp[sc][b][h] = sum_{s in chunk} w[b][s] * key[s][b][h]
// ---------------------------------------------------------------------------
__global__ void ctx_kernel(const float* __restrict__ key,
                           const float* __restrict__ w) {
    int schunk = blockIdx.x;
    int b      = blockIdx.y;
    int tid    = threadIdx.x;
    __shared__ float ws[128];
    if (tid < 128) ws[tid] = w[b * S_ + schunk * 128 + tid];
    __syncthreads();

    int h4 = tid * 4;
    const float* kb = key + ((schunk * 128) * B_ + b) * H_ + h4;
    float4 acc = make_float4(0.f, 0.f, 0.f, 0.f);
#pragma unroll 8
    for (int ss = 0; ss < 128; ss++) {
        float4 kv = *(const float4*)(kb + ss * B_ * H_);
        float wv  = ws[ss];
        acc.x = fmaf(wv, kv.x, acc.x);
        acc.y = fmaf(wv, kv.y, acc.y);
        acc.z = fmaf(wv, kv.z, acc.z);
        acc.w = fmaf(wv, kv.w, acc.w);
    }
    *(float4*)&g_ctxp[(schunk * B_ + b) * H_ + h4] = acc;
}

// Kernel 5: reduce the 16 context partials -> d_out[0 : B*H]
__global__ void ctx_reduce(float* __restrict__ out) {
    int i = blockIdx.x * 256 + threadIdx.x;    // 0..32767
    float v = 0.f;
#pragma unroll
    for (int sc = 0; sc < SC_; sc++)
        v += g_ctxp[sc * B_ * H_ + i];
    out[i] = v;
}

// ---------------------------------------------------------------------------
extern "C" void kernel_launch(void* const* d_in, const int* in_sizes, int n_in,
                              void* d_out, int out_size) {
    const float* query = (const float*)d_in[0];
    const float* key   = (const float*)d_in[1];
    const float* Wa_w  = (const float*)d_in[2];
    const float* Wa_b  = (const float*)d_in[3];
    const float* Ua_w  = (const float*)d_in[4];
    const float* Ua_b  = (const float*)d_in[5];
    const float* va_w  = (const float*)d_in[6];
    // d_in[7] = va_b : constant shift before softmax -> softmax-invariant, unused.

    float* out = (float*)d_out;

    // weights destination: after context if the output holds both, else scratch
    float* wdst;
    if (out_size >= B_ * H_ + B_ * S_) {
        wdst = out + B_ * H_;
    } else {
        void* p = nullptr;
        cudaGetSymbolAddress(&p, g_wfallback);
        wdst = (float*)p;
    }

    qw_kernel   <<<dim3(H_ / 256, B_), 256>>>(query, Wa_w, Wa_b, Ua_b);
    energy_kernel<<<dim3(NB_, M_ / 128), 256>>>(key, Ua_w, va_w);
    softmax_kernel<<<B_, 256>>>(wdst);
    ctx_kernel  <<<dim3(SC_, B_), 256>>>(key, wdst);
    ctx_reduce  <<<(B_ * H_) / 256, 256>>>(out);
}